// round 1
// baseline (speedup 1.0000x reference)
#include <cuda_runtime.h>
#include <cuda_bf16.h>

#define MMAX 200704
#define NB 256   // number of blocks for GN stats kernels (fixed)

// ---------------- scratch (device globals; no allocation allowed) ----------------
__device__ float g_A[(size_t)MMAX * 128];   // h_sum -> h_d
__device__ float g_B[(size_t)MMAX * 128];   // x_sum -> x_d
__device__ float g_C[(size_t)MMAX * 256];   // h1
__device__ float g_D[(size_t)MMAX * 256];   // h2
__device__ float g_cnt[MMAX];
__device__ float g_part[2 * NB * 256];      // GN partial sums (reused gn1/gn2)
__device__ float g_scale[256];              // per-channel scale (reused gn1/gn2)
__device__ float g_shift[256];              // per-channel shift

__device__ __forceinline__ float silu_f(float x) { return x / (1.f + __expf(-x)); }

// ---------------- utility ----------------
__global__ void zero_kernel(float* p, size_t n) {
    size_t i = (size_t)blockIdx.x * blockDim.x + threadIdx.x;
    size_t stride = (size_t)gridDim.x * blockDim.x;
    for (; i < n; i += stride) p[i] = 0.f;
}

// ---------------- GroupNorm stats: stage 1 (per-block per-channel partials) -----
template <int C>
__global__ void gn_stats(const float* __restrict__ x, int n, float* __restrict__ part) {
    const int RPB = 256 / C;                 // rows per block-iteration (2 for C=128, 1 for C=256)
    int tid = threadIdx.x;
    int c = tid % C;
    int rsub = tid / C;
    float s = 0.f, q = 0.f;
    for (long r = (long)blockIdx.x * RPB + rsub; r < n; r += (long)gridDim.x * RPB) {
        float v = x[r * C + c];
        s += v; q += v * v;
    }
    if (C == 128) {
        __shared__ float sh[512];
        sh[tid] = s; sh[256 + tid] = q;
        __syncthreads();
        if (tid < 128) {
            s = sh[tid] + sh[tid + 128];
            q = sh[256 + tid] + sh[256 + tid + 128];
            part[blockIdx.x * C + c] = s;
            part[NB * C + blockIdx.x * C + c] = q;
        }
    } else {
        part[blockIdx.x * C + c] = s;
        part[NB * C + blockIdx.x * C + c] = q;
    }
}

// ---------------- GroupNorm stats: stage 2 (finalize -> per-channel scale/shift) -
template <int C, int CPG>
__global__ void gn_finalize(const float* __restrict__ part, const float* __restrict__ w,
                            const float* __restrict__ b, float rcount) {
    int c = threadIdx.x;  // launched with C threads
    float s = 0.f, q = 0.f;
    for (int blk = 0; blk < NB; blk++) {
        s += part[blk * C + c];
        q += part[NB * C + blk * C + c];
    }
    __shared__ float cs[256], cq[256];
    cs[c] = s; cq[c] = q;
    __syncthreads();
    __shared__ float mu[32], rs[32];
    if (c < C / CPG) {
        float S = 0.f, Q = 0.f;
        for (int j = 0; j < CPG; j++) { S += cs[c * CPG + j]; Q += cq[c * CPG + j]; }
        float m = S * rcount;
        float v = Q * rcount - m * m;
        mu[c] = m;
        rs[c] = rsqrtf(v + 1e-5f);
    }
    __syncthreads();
    int g = c / CPG;
    float sc = w[c] * rs[g];
    g_scale[c] = sc;
    g_shift[c] = b[c] - mu[g] * sc;
}

// ---------------- GN1+SiLU + segment-sum downsample (atomic scatter) -------------
__global__ void downsample_kernel(const float* __restrict__ feats,
                                  const int* __restrict__ seg, int n) {
    long t = (long)blockIdx.x * blockDim.x + threadIdx.x;
    if (t >= (long)n * 32) return;
    int row = (int)(t >> 5);
    int q = (int)(t & 31);
    int c = q * 4;
    int s = seg[row];
    float4 f = *(const float4*)(feats + (long)row * 128 + c);
    float4 sc = *(const float4*)(g_scale + c);
    float4 sh = *(const float4*)(g_shift + c);
    float h0 = silu_f(f.x * sc.x + sh.x);
    float h1 = silu_f(f.y * sc.y + sh.y);
    float h2 = silu_f(f.z * sc.z + sh.z);
    float h3 = silu_f(f.w * sc.w + sh.w);
    float* hp = g_A + (long)s * 128 + c;
    float* xp = g_B + (long)s * 128 + c;
    atomicAdd(hp + 0, h0); atomicAdd(hp + 1, h1);
    atomicAdd(hp + 2, h2); atomicAdd(hp + 3, h3);
    atomicAdd(xp + 0, f.x); atomicAdd(xp + 1, f.y);
    atomicAdd(xp + 2, f.z); atomicAdd(xp + 3, f.w);
    if (q == 0) atomicAdd(g_cnt + s, 1.f);
}

__global__ void finalize_down(int M) {
    long t = (long)blockIdx.x * blockDim.x + threadIdx.x;
    if (t >= (long)M * 32) return;
    int row = (int)(t >> 5);
    int c = (int)(t & 31) * 4;
    float ic = 1.f / fmaxf(g_cnt[row], 1.f);
    float4* a = (float4*)(g_A + (long)row * 128 + c);
    float4 va = *a; va.x *= ic; va.y *= ic; va.z *= ic; va.w *= ic; *a = va;
    float4* bb = (float4*)(g_B + (long)row * 128 + c);
    float4 vb = *bb; vb.x *= ic; vb.y *= ic; vb.z *= ic; vb.w *= ic; *bb = vb;
}

// ---------------- apply GN2 + SiLU elementwise (h1 -> h2) ------------------------
__global__ void apply_gn2(int M) {
    long t = (long)blockIdx.x * blockDim.x + threadIdx.x;
    if (t >= (long)M * 64) return;
    int row = (int)(t >> 6);
    int c = (int)(t & 63) * 4;
    float4 v = *(const float4*)(g_C + (long)row * 256 + c);
    float4 sc = *(const float4*)(g_scale + c);
    float4 sh = *(const float4*)(g_shift + c);
    float4 o;
    o.x = silu_f(v.x * sc.x + sh.x);
    o.y = silu_f(v.y * sc.y + sh.y);
    o.z = silu_f(v.z * sc.z + sh.z);
    o.w = silu_f(v.w * sc.w + sh.w);
    *(float4*)(g_D + (long)row * 256 + c) = o;
}

// ---------------- 27-tap gather GEMM: out[i,:] (+)= sum_k x[nbr[i,k],:] @ W[k] ---
// Block: 256 threads; tile = 32 rows x 256 cols. Thread (ty,tx): rows ty*4..+3,
// cols {tx*4..+3} U {128+tx*4..+3} (conflict-free LDS.128 on W).
template <int CIN, bool ADDOUT>
__global__ __launch_bounds__(256) void conv27(const float* __restrict__ x,
                                              const float* __restrict__ W,
                                              const float* __restrict__ bias,
                                              const int* __restrict__ nbr,
                                              float* __restrict__ out, int M) {
    __shared__ float xs[32][CIN];
    __shared__ float ws[8][256];
    __shared__ int nid[32];
    const int tid = threadIdx.x;
    const int base = blockIdx.x * 32;
    const int ty = tid >> 5;   // 0..7 -> rows ty*4..ty*4+3
    const int tx = tid & 31;   // 0..31 -> cols tx*4 and 128+tx*4

    float acc[4][8];
#pragma unroll
    for (int i = 0; i < 4; i++)
#pragma unroll
        for (int j = 0; j < 8; j++) acc[i][j] = 0.f;

    for (int k = 0; k < 27; k++) {
        __syncthreads();  // previous iteration's xs/ws reads done
        if (tid < 32) {
            int r = base + tid;
            nid[tid] = (r < M) ? nbr[(long)r * 27 + k] : -1;
        }
        __syncthreads();
        // gather 32 rows of x into smem (zeros for missing neighbors)
        for (int l = tid; l < 32 * (CIN / 4); l += 256) {
            int r = l / (CIN / 4);
            int c4 = l % (CIN / 4);
            int src = nid[r];
            float4 v = make_float4(0.f, 0.f, 0.f, 0.f);
            if (src >= 0) v = *(const float4*)(x + (long)src * CIN + c4 * 4);
            *(float4*)&xs[r][c4 * 4] = v;
        }
        for (int c0 = 0; c0 < CIN; c0 += 8) {
            __syncthreads();  // gather visible / previous ws reads done
#pragma unroll
            for (int l = tid; l < 8 * 64; l += 256) {
                int rr = l >> 6;
                int cc4 = l & 63;
                *(float4*)&ws[rr][cc4 * 4] =
                    *(const float4*)(W + ((long)k * CIN + c0 + rr) * 256 + cc4 * 4);
            }
            __syncthreads();
#pragma unroll
            for (int cc = 0; cc < 8; cc++) {
                float x0 = xs[ty * 4 + 0][c0 + cc];
                float x1 = xs[ty * 4 + 1][c0 + cc];
                float x2 = xs[ty * 4 + 2][c0 + cc];
                float x3 = xs[ty * 4 + 3][c0 + cc];
                float4 w0 = *(float4*)&ws[cc][tx * 4];
                float4 w1 = *(float4*)&ws[cc][128 + tx * 4];
                acc[0][0] += x0 * w0.x; acc[0][1] += x0 * w0.y; acc[0][2] += x0 * w0.z; acc[0][3] += x0 * w0.w;
                acc[0][4] += x0 * w1.x; acc[0][5] += x0 * w1.y; acc[0][6] += x0 * w1.z; acc[0][7] += x0 * w1.w;
                acc[1][0] += x1 * w0.x; acc[1][1] += x1 * w0.y; acc[1][2] += x1 * w0.z; acc[1][3] += x1 * w0.w;
                acc[1][4] += x1 * w1.x; acc[1][5] += x1 * w1.y; acc[1][6] += x1 * w1.z; acc[1][7] += x1 * w1.w;
                acc[2][0] += x2 * w0.x; acc[2][1] += x2 * w0.y; acc[2][2] += x2 * w0.z; acc[2][3] += x2 * w0.w;
                acc[2][4] += x2 * w1.x; acc[2][5] += x2 * w1.y; acc[2][6] += x2 * w1.z; acc[2][7] += x2 * w1.w;
                acc[3][0] += x3 * w0.x; acc[3][1] += x3 * w0.y; acc[3][2] += x3 * w0.z; acc[3][3] += x3 * w0.w;
                acc[3][4] += x3 * w1.x; acc[3][5] += x3 * w1.y; acc[3][6] += x3 * w1.z; acc[3][7] += x3 * w1.w;
            }
        }
    }
    // epilogue
    float4 b0 = *(const float4*)(bias + tx * 4);
    float4 b1 = *(const float4*)(bias + 128 + tx * 4);
#pragma unroll
    for (int i = 0; i < 4; i++) {
        int r = base + ty * 4 + i;
        if (r < M) {
            float* o0 = out + (long)r * 256 + tx * 4;
            float* o1 = out + (long)r * 256 + 128 + tx * 4;
            float4 v0 = make_float4(acc[i][0] + b0.x, acc[i][1] + b0.y,
                                    acc[i][2] + b0.z, acc[i][3] + b0.w);
            float4 v1 = make_float4(acc[i][4] + b1.x, acc[i][5] + b1.y,
                                    acc[i][6] + b1.z, acc[i][7] + b1.w);
            if (ADDOUT) {
                float4 p0 = *(float4*)o0;
                float4 p1 = *(float4*)o1;
                v0.x += p0.x; v0.y += p0.y; v0.z += p0.z; v0.w += p0.w;
                v1.x += p1.x; v1.y += p1.y; v1.z += p1.z; v1.w += p1.w;
            }
            *(float4*)o0 = v0;
            *(float4*)o1 = v1;
        }
    }
}

// ---------------- skip: out = x_d @ Wskip + bskip (dense rows, 128 -> 256) -------
__global__ __launch_bounds__(256) void skip_gemm(const float* __restrict__ x,
                                                 const float* __restrict__ W,
                                                 const float* __restrict__ bias,
                                                 float* __restrict__ out, int M) {
    __shared__ float xs[32][128];
    __shared__ float ws[8][256];
    const int tid = threadIdx.x;
    const int base = blockIdx.x * 32;
    const int ty = tid >> 5;
    const int tx = tid & 31;

    float acc[4][8];
#pragma unroll
    for (int i = 0; i < 4; i++)
#pragma unroll
        for (int j = 0; j < 8; j++) acc[i][j] = 0.f;

    // load 32 rows of x_d
    for (int l = tid; l < 32 * 32; l += 256) {
        int r = l / 32;
        int c4 = l % 32;
        int src = base + r;
        float4 v = make_float4(0.f, 0.f, 0.f, 0.f);
        if (src < M) v = *(const float4*)(x + (long)src * 128 + c4 * 4);
        *(float4*)&xs[r][c4 * 4] = v;
    }
    for (int c0 = 0; c0 < 128; c0 += 8) {
        __syncthreads();
#pragma unroll
        for (int l = tid; l < 8 * 64; l += 256) {
            int rr = l >> 6;
            int cc4 = l & 63;
            *(float4*)&ws[rr][cc4 * 4] = *(const float4*)(W + (long)(c0 + rr) * 256 + cc4 * 4);
        }
        __syncthreads();
#pragma unroll
        for (int cc = 0; cc < 8; cc++) {
            float x0 = xs[ty * 4 + 0][c0 + cc];
            float x1 = xs[ty * 4 + 1][c0 + cc];
            float x2 = xs[ty * 4 + 2][c0 + cc];
            float x3 = xs[ty * 4 + 3][c0 + cc];
            float4 w0 = *(float4*)&ws[cc][tx * 4];
            float4 w1 = *(float4*)&ws[cc][128 + tx * 4];
            acc[0][0] += x0 * w0.x; acc[0][1] += x0 * w0.y; acc[0][2] += x0 * w0.z; acc[0][3] += x0 * w0.w;
            acc[0][4] += x0 * w1.x; acc[0][5] += x0 * w1.y; acc[0][6] += x0 * w1.z; acc[0][7] += x0 * w1.w;
            acc[1][0] += x1 * w0.x; acc[1][1] += x1 * w0.y; acc[1][2] += x1 * w0.z; acc[1][3] += x1 * w0.w;
            acc[1][4] += x1 * w1.x; acc[1][5] += x1 * w1.y; acc[1][6] += x1 * w1.z; acc[1][7] += x1 * w1.w;
            acc[2][0] += x2 * w0.x; acc[2][1] += x2 * w0.y; acc[2][2] += x2 * w0.z; acc[2][3] += x2 * w0.w;
            acc[2][4] += x2 * w1.x; acc[2][5] += x2 * w1.y; acc[2][6] += x2 * w1.z; acc[2][7] += x2 * w1.w;
            acc[3][0] += x3 * w0.x; acc[3][1] += x3 * w0.y; acc[3][2] += x3 * w0.z; acc[3][3] += x3 * w0.w;
            acc[3][4] += x3 * w1.x; acc[3][5] += x3 * w1.y; acc[3][6] += x3 * w1.z; acc[3][7] += x3 * w1.w;
        }
    }
    float4 b0 = *(const float4*)(bias + tx * 4);
    float4 b1 = *(const float4*)(bias + 128 + tx * 4);
#pragma unroll
    for (int i = 0; i < 4; i++) {
        int r = base + ty * 4 + i;
        if (r < M) {
            *(float4*)(out + (long)r * 256 + tx * 4) =
                make_float4(acc[i][0] + b0.x, acc[i][1] + b0.y, acc[i][2] + b0.z, acc[i][3] + b0.w);
            *(float4*)(out + (long)r * 256 + 128 + tx * 4) =
                make_float4(acc[i][4] + b1.x, acc[i][5] + b1.y, acc[i][6] + b1.z, acc[i][7] + b1.w);
        }
    }
}

// ---------------- launch ----------------
extern "C" void kernel_launch(void* const* d_in, const int* in_sizes, int n_in,
                              void* d_out, int out_size) {
    const float* feats = (const float*)d_in[0];
    const float* gn1_w = (const float*)d_in[1];
    const float* gn1_b = (const float*)d_in[2];
    const float* W1    = (const float*)d_in[3];
    const float* b1    = (const float*)d_in[4];
    const float* gn2_w = (const float*)d_in[5];
    const float* gn2_b = (const float*)d_in[6];
    const float* W2    = (const float*)d_in[7];
    const float* b2    = (const float*)d_in[8];
    const float* Wskip = (const float*)d_in[9];
    const float* bskip = (const float*)d_in[10];
    const int* pool_seg = (const int*)d_in[11];
    const int* nbr_idx  = (const int*)d_in[12];
    float* out = (float*)d_out;

    int N = in_sizes[0] / 128;
    int M = in_sizes[12] / 27;

    float *A, *B, *C, *D, *cnt, *part;
    cudaGetSymbolAddress((void**)&A, g_A);
    cudaGetSymbolAddress((void**)&B, g_B);
    cudaGetSymbolAddress((void**)&C, g_C);
    cudaGetSymbolAddress((void**)&D, g_D);
    cudaGetSymbolAddress((void**)&cnt, g_cnt);
    cudaGetSymbolAddress((void**)&part, g_part);

    // zero accumulators (graph replays -> must re-zero every launch)
    zero_kernel<<<4096, 256>>>(A, (size_t)M * 128);
    zero_kernel<<<4096, 256>>>(B, (size_t)M * 128);
    zero_kernel<<<256, 256>>>(cnt, (size_t)M);

    // GN1 stats + finalize
    gn_stats<128><<<NB, 256>>>(feats, N, part);
    gn_finalize<128, 4><<<1, 128>>>(part, gn1_w, gn1_b, 1.f / ((float)N * 4.f));

    // GN1 apply + SiLU + segment sums
    long dthreads = (long)N * 32;
    downsample_kernel<<<(int)((dthreads + 255) / 256), 256>>>(feats, pool_seg, N);
    long fthreads = (long)M * 32;
    finalize_down<<<(int)((fthreads + 255) / 256), 256>>>(M);

    // conv1: h1 = conv(h_d, W1) + b1
    int nconv = (M + 31) / 32;
    conv27<128, false><<<nconv, 256>>>(A, W1, b1, nbr_idx, C, M);

    // GN2 stats + finalize + apply
    gn_stats<256><<<NB, 256>>>(C, M, part);
    gn_finalize<256, 8><<<1, 256>>>(part, gn2_w, gn2_b, 1.f / ((float)M * 8.f));
    long athreads = (long)M * 64;
    apply_gn2<<<(int)((athreads + 255) / 256), 256>>>(M);

    // skip = x_d @ Wskip + bskip  (writes out)
    skip_gemm<<<nconv, 256>>>(B, Wskip, bskip, out, M);

    // conv2: out += conv(h2, W2) + b2
    conv27<256, true><<<nconv, 256>>>(D, W2, b2, nbr_idx, out, M);
}

// round 3
// speedup vs baseline: 1.8015x; 1.8015x over previous
#include <cuda_runtime.h>
#include <cuda_bf16.h>
#include <cstdint>

#define MMAX 200704
#define NB 256

typedef __nv_bfloat16 bf16;

// ---------------- scratch (device globals; no allocation allowed) ----------------
__device__ float g_A[(size_t)MMAX * 128];   // h segment-sum accumulator
__device__ float g_B[(size_t)MMAX * 128];   // x segment-sum accumulator
__device__ float g_C[(size_t)MMAX * 256];   // h1 (conv1 out, fp32 for GN2 stats)
__device__ float g_cnt[MMAX];
__device__ float g_part[2 * NB * 256];
__device__ float g_scale[256];
__device__ float g_shift[256];
// bf16 hi/lo operand planes
__device__ bf16 g_hdh[(size_t)MMAX * 128];
__device__ bf16 g_hdl[(size_t)MMAX * 128];
__device__ bf16 g_xdh[(size_t)MMAX * 128];
__device__ bf16 g_xdl[(size_t)MMAX * 128];
__device__ bf16 g_h2h[(size_t)MMAX * 256];
__device__ bf16 g_h2l[(size_t)MMAX * 256];
__device__ bf16 g_W1h[27 * 256 * 128];      // [k][n][c]
__device__ bf16 g_W1l[27 * 256 * 128];
__device__ bf16 g_W2h[27 * 256 * 256];
__device__ bf16 g_W2l[27 * 256 * 256];
__device__ bf16 g_WSh[256 * 128];
__device__ bf16 g_WSl[256 * 128];

__device__ __forceinline__ float silu_f(float x) { return x / (1.f + __expf(-x)); }

__device__ __forceinline__ uint32_t smem_u32(const void* p) {
    uint32_t a;
    asm("{ .reg .u64 t; cvta.to.shared.u64 t, %1; cvt.u32.u64 %0, t; }" : "=r"(a) : "l"(p));
    return a;
}
__device__ __forceinline__ void cp_async16(uint32_t dst, const void* src) {
    asm volatile("cp.async.cg.shared.global [%0], [%1], 16;" :: "r"(dst), "l"(src));
}
__device__ __forceinline__ void cp_commit() {
    asm volatile("cp.async.commit_group;" ::: "memory");
}
__device__ __forceinline__ void cp_wait0() {
    asm volatile("cp.async.wait_group 0;" ::: "memory");
}
__device__ __forceinline__ void ldmx4(uint32_t* r, uint32_t addr) {
    asm volatile("ldmatrix.sync.aligned.m8n8.x4.shared.b16 {%0,%1,%2,%3}, [%4];"
                 : "=r"(r[0]), "=r"(r[1]), "=r"(r[2]), "=r"(r[3]) : "r"(addr));
}
__device__ __forceinline__ void mma16816(float* d, const uint32_t* a, const uint32_t* b) {
    asm volatile(
        "mma.sync.aligned.m16n8k16.row.col.f32.bf16.bf16.f32 "
        "{%0,%1,%2,%3}, {%4,%5,%6,%7}, {%8,%9}, {%0,%1,%2,%3};"
        : "+f"(d[0]), "+f"(d[1]), "+f"(d[2]), "+f"(d[3])
        : "r"(a[0]), "r"(a[1]), "r"(a[2]), "r"(a[3]), "r"(b[0]), "r"(b[1]));
}

// ---------------- small kernels ----------------
__global__ void zero_kernel(float* p, size_t n) {
    size_t i = (size_t)blockIdx.x * blockDim.x + threadIdx.x;
    size_t s = (size_t)gridDim.x * blockDim.x;
    for (; i < n; i += s) p[i] = 0.f;
}

template <int C>
__global__ void gn_stats(const float* __restrict__ x, int n, float* __restrict__ part) {
    const int RPB = 256 / C;
    int tid = threadIdx.x;
    int c = tid % C;
    int rsub = tid / C;
    float s = 0.f, q = 0.f;
    for (long r = (long)blockIdx.x * RPB + rsub; r < n; r += (long)gridDim.x * RPB) {
        float v = x[r * C + c];
        s += v; q += v * v;
    }
    if (C == 128) {
        __shared__ float sh[512];
        sh[tid] = s; sh[256 + tid] = q;
        __syncthreads();
        if (tid < 128) {
            s = sh[tid] + sh[tid + 128];
            q = sh[256 + tid] + sh[256 + tid + 128];
            part[blockIdx.x * C + c] = s;
            part[NB * C + blockIdx.x * C + c] = q;
        }
    } else {
        part[blockIdx.x * C + c] = s;
        part[NB * C + blockIdx.x * C + c] = q;
    }
}

template <int C, int CPG>
__global__ void gn_finalize(const float* __restrict__ part, const float* __restrict__ w,
                            const float* __restrict__ b, float rcount) {
    int c = threadIdx.x;
    float s = 0.f, q = 0.f;
    for (int blk = 0; blk < NB; blk++) {
        s += part[blk * C + c];
        q += part[NB * C + blk * C + c];
    }
    __shared__ float cs[256], cq[256];
    cs[c] = s; cq[c] = q;
    __syncthreads();
    __shared__ float mu[32], rs[32];
    if (c < C / CPG) {
        float S = 0.f, Q = 0.f;
        for (int j = 0; j < CPG; j++) { S += cs[c * CPG + j]; Q += cq[c * CPG + j]; }
        float m = S * rcount;
        float v = Q * rcount - m * m;
        mu[c] = m;
        rs[c] = rsqrtf(v + 1e-5f);
    }
    __syncthreads();
    int g = c / CPG;
    float sc = w[c] * rs[g];
    g_scale[c] = sc;
    g_shift[c] = b[c] - mu[g] * sc;
}

__global__ void downsample_kernel(const float* __restrict__ feats,
                                  const int* __restrict__ seg, int n) {
    long t = (long)blockIdx.x * blockDim.x + threadIdx.x;
    if (t >= (long)n * 32) return;
    int row = (int)(t >> 5);
    int q = (int)(t & 31);
    int c = q * 4;
    int s = seg[row];
    float4 f = *(const float4*)(feats + (long)row * 128 + c);
    float4 sc = *(const float4*)(g_scale + c);
    float4 sh = *(const float4*)(g_shift + c);
    float h0 = silu_f(f.x * sc.x + sh.x);
    float h1 = silu_f(f.y * sc.y + sh.y);
    float h2 = silu_f(f.z * sc.z + sh.z);
    float h3 = silu_f(f.w * sc.w + sh.w);
    float* hp = g_A + (long)s * 128 + c;
    float* xp = g_B + (long)s * 128 + c;
    atomicAdd(hp + 0, h0); atomicAdd(hp + 1, h1);
    atomicAdd(hp + 2, h2); atomicAdd(hp + 3, h3);
    atomicAdd(xp + 0, f.x); atomicAdd(xp + 1, f.y);
    atomicAdd(xp + 2, f.z); atomicAdd(xp + 3, f.w);
    if (q == 0) atomicAdd(g_cnt + s, 1.f);
}

__device__ __forceinline__ void split_store(bf16* ph, bf16* pl, size_t idx, float v) {
    bf16 h = __float2bfloat16(v);
    ph[idx] = h;
    pl[idx] = __float2bfloat16(v - __bfloat162float(h));
}

__global__ void finalize_down(int M) {
    long t = (long)blockIdx.x * blockDim.x + threadIdx.x;
    if (t >= (long)M * 32) return;
    int row = (int)(t >> 5);
    int c = (int)(t & 31) * 4;
    float ic = 1.f / fmaxf(g_cnt[row], 1.f);
    size_t base = (size_t)row * 128 + c;
    float4 va = *(const float4*)(g_A + base);
    float4 vb = *(const float4*)(g_B + base);
    split_store(g_hdh, g_hdl, base + 0, va.x * ic);
    split_store(g_hdh, g_hdl, base + 1, va.y * ic);
    split_store(g_hdh, g_hdl, base + 2, va.z * ic);
    split_store(g_hdh, g_hdl, base + 3, va.w * ic);
    split_store(g_xdh, g_xdl, base + 0, vb.x * ic);
    split_store(g_xdh, g_xdl, base + 1, vb.y * ic);
    split_store(g_xdh, g_xdl, base + 2, vb.z * ic);
    split_store(g_xdh, g_xdl, base + 3, vb.w * ic);
}

__global__ void apply_gn2(int M) {
    long t = (long)blockIdx.x * blockDim.x + threadIdx.x;
    if (t >= (long)M * 64) return;
    int row = (int)(t >> 6);
    int c = (int)(t & 63) * 4;
    size_t base = (size_t)row * 256 + c;
    float4 v = *(const float4*)(g_C + base);
    float4 sc = *(const float4*)(g_scale + c);
    float4 sh = *(const float4*)(g_shift + c);
    split_store(g_h2h, g_h2l, base + 0, silu_f(v.x * sc.x + sh.x));
    split_store(g_h2h, g_h2l, base + 1, silu_f(v.y * sc.y + sh.y));
    split_store(g_h2h, g_h2l, base + 2, silu_f(v.z * sc.z + sh.z));
    split_store(g_h2h, g_h2l, base + 3, silu_f(v.w * sc.w + sh.w));
}

template <int CIN>
__global__ void prep_w(const float* __restrict__ W, bf16* __restrict__ wh,
                       bf16* __restrict__ wl, int total) {
    int idx = blockIdx.x * blockDim.x + threadIdx.x;
    int stride = gridDim.x * blockDim.x;
    for (; idx < total; idx += stride) {
        int c = idx % CIN;
        int n = (idx / CIN) % 256;
        int k = idx / (CIN * 256);
        float v = W[((size_t)k * CIN + c) * 256 + n];
        bf16 h = __float2bfloat16(v);
        wh[idx] = h;
        wl[idx] = __float2bfloat16(v - __bfloat162float(h));
    }
}

// ---------------- HMMA gather-conv (m16n8k16 bf16, 3-term hi/lo split) ----------
// CTA 256 thr / 8 warps; tile 64(M) x 256(N); warp grid 2x4 -> 32x64 per warp.
// A staged per tap (hi+lo, XOR-swizzled rows); W streamed in K=32 chunks via
// 2-stage cp.async pipeline (rows padded to 80B => conflict-free ldmatrix).
template <int CIN, bool FUSE_SKIP>
__global__ __launch_bounds__(256, 1) void conv_hmma(
    const bf16* __restrict__ xh, const bf16* __restrict__ xl,
    const bf16* __restrict__ wh, const bf16* __restrict__ wl,
    const bf16* __restrict__ sxh, const bf16* __restrict__ sxl,
    const bf16* __restrict__ swh, const bf16* __restrict__ swl,
    const float* __restrict__ bias, const float* __restrict__ bias2,
    const int* __restrict__ nbr, float* __restrict__ out, int M) {
    extern __shared__ char smem[];
    constexpr int APL = 64 * CIN * 2;     // bytes per A plane
    constexpr int BOFF = 2 * APL;
    constexpr int BPL = 256 * 80;         // bytes per B plane (padded rows)
    constexpr int BUFSZ = 2 * BPL;
    constexpr int NCH = CIN / 32;
    const int TC = 27 * NCH + (FUSE_SKIP ? 4 : 0);
    int* nid = (int*)(smem + BOFF + 2 * BUFSZ);
    const uint32_t sbase = smem_u32(smem);
    const int tid = threadIdx.x;
    const int mbase = blockIdx.x * 64;
    const int lane = tid & 31;
    const int wm = (tid >> 5) >> 2;       // 0..1
    const int wn = (tid >> 5) & 3;        // 0..3

    float d[2][8][4];
#pragma unroll
    for (int a = 0; a < 2; a++)
#pragma unroll
        for (int b = 0; b < 8; b++)
#pragma unroll
            for (int c = 0; c < 4; c++) d[a][b][c] = 0.f;

    // ---- issue B chunk i into buffer i&1 (both planes), one commit group ----
    auto issueB = [&](int i) {
        int c0, cin;
        const bf16 *ph, *pl;
        if (i < 27 * NCH) {
            int tap = i / NCH;
            c0 = (i % NCH) * 32; cin = CIN;
            ph = wh + (size_t)tap * 256 * CIN;
            pl = wl + (size_t)tap * 256 * CIN;
        } else {
            c0 = (i - 27 * NCH) * 32; cin = 128;
            ph = swh; pl = swl;
        }
        uint32_t dstb = sbase + BOFF + (i & 1) * BUFSZ;
        for (int u = tid; u < 2048; u += 256) {
            int plane = u >> 10, n = (u >> 2) & 255, uu = u & 3;
            const bf16* src = (plane ? pl : ph) + (size_t)n * cin + c0 + uu * 8;
            cp_async16(dstb + plane * BPL + n * 80 + uu * 16, src);
        }
        cp_commit();
    };

    // ---- gather A rows (hi+lo) for a tap into swizzled smem ----
    auto gatherA = [&](int tap) {
        const bool skiptap = FUSE_SKIP && (tap == 27);
        const int cin = skiptap ? 128 : CIN;
        const int ru = cin / 8;
        const bf16* ph = skiptap ? sxh : xh;
        const bf16* pl = skiptap ? sxl : xl;
        if (tid < 64) {
            int r = mbase + tid;
            nid[tid] = skiptap ? ((r < M) ? r : -1)
                               : ((r < M) ? nbr[(size_t)r * 27 + tap] : -1);
        }
        __syncthreads();
        const int TU = 2 * 64 * ru;
        for (int idx = tid; idx < TU; idx += 256) {
            int plane = idx / (64 * ru);
            int rem = idx - plane * 64 * ru;
            int r = rem / ru, u = rem - r * ru;
            int src = nid[r];
            uint4 v = {0u, 0u, 0u, 0u};
            if (src >= 0) v = *(const uint4*)((plane ? pl : ph) + (size_t)src * cin + u * 8);
            int swu = (u & ~7) | ((u & 7) ^ (r & 7));
            *(uint4*)(smem + plane * APL + r * (CIN * 2) + swu * 16) = v;
        }
        __syncthreads();
    };

    // ---- main pipeline ----
    issueB(0);
    for (int i = 0; i < TC; i++) {
        bool tapstart = (i < 27 * NCH) ? ((i % NCH) == 0) : (i == 27 * NCH);
        cp_wait0();          // chunk i resident
        __syncthreads();     // all threads past compute(i-1)
        if (tapstart) gatherA((i < 27 * NCH) ? (i / NCH) : 27);
        if (i + 1 < TC) issueB(i + 1);  // overlaps compute(i)

        const int kb0 = (i < 27 * NCH) ? ((i % NCH) * 4) : ((i - 27 * NCH) * 4);
        const uint32_t bb = sbase + BOFF + (i & 1) * BUFSZ;
#pragma unroll
        for (int ks = 0; ks < 2; ks++) {
            uint32_t ah[2][4], al[2][4], bh[4][4], bl[4][4];
            const int kunit = kb0 + ks * 2 + ((lane >> 4) & 1);
            // A fragments (both planes, 2 m-tiles)
#pragma unroll
            for (int mt = 0; mt < 2; mt++) {
                int row = wm * 32 + mt * 16 + (lane & 15);
                int swu = (kunit & ~7) | ((kunit & 7) ^ (row & 7));
                uint32_t ad = sbase + row * (CIN * 2) + swu * 16;
                ldmx4(ah[mt], ad);
                ldmx4(al[mt], ad + APL);
            }
            // B fragments (both planes, 8 n-tiles as 4 x4-loads)
            const int brow_off = (lane & 7) + ((lane & 16) ? 8 : 0);
            const int bunit = ks * 2 + ((lane >> 3) & 1);
#pragma unroll
            for (int p = 0; p < 4; p++) {
                int n = wn * 64 + p * 16 + brow_off;
                uint32_t bd = bb + n * 80 + bunit * 16;
                ldmx4(bh[p], bd);
                ldmx4(bl[p], bd + BPL);
            }
            // 3-term MMAs
#pragma unroll
            for (int mt = 0; mt < 2; mt++)
#pragma unroll
                for (int p = 0; p < 4; p++) {
                    mma16816(d[mt][2 * p + 0], ah[mt], &bh[p][0]);
                    mma16816(d[mt][2 * p + 1], ah[mt], &bh[p][2]);
                    mma16816(d[mt][2 * p + 0], ah[mt], &bl[p][0]);
                    mma16816(d[mt][2 * p + 1], ah[mt], &bl[p][2]);
                    mma16816(d[mt][2 * p + 0], al[mt], &bh[p][0]);
                    mma16816(d[mt][2 * p + 1], al[mt], &bh[p][2]);
                }
        }
    }

    // ---- epilogue: direct global stores (float2 per fragment row) ----
#pragma unroll
    for (int mt = 0; mt < 2; mt++) {
        int r0 = mbase + wm * 32 + mt * 16 + lane / 4;
#pragma unroll
        for (int t = 0; t < 8; t++) {
            int gc = wn * 64 + t * 8 + (lane % 4) * 2;
            float bx = bias[gc], by = bias[gc + 1];
            if (FUSE_SKIP) { bx += bias2[gc]; by += bias2[gc + 1]; }
            if (r0 < M) {
                float2 v = {d[mt][t][0] + bx, d[mt][t][1] + by};
                *(float2*)(out + (size_t)r0 * 256 + gc) = v;
            }
            if (r0 + 8 < M) {
                float2 v = {d[mt][t][2] + bx, d[mt][t][3] + by};
                *(float2*)(out + (size_t)(r0 + 8) * 256 + gc) = v;
            }
        }
    }
}

// ---------------- launch ----------------
extern "C" void kernel_launch(void* const* d_in, const int* in_sizes, int n_in,
                              void* d_out, int out_size) {
    const float* feats = (const float*)d_in[0];
    const float* gn1_w = (const float*)d_in[1];
    const float* gn1_b = (const float*)d_in[2];
    const float* W1    = (const float*)d_in[3];
    const float* b1    = (const float*)d_in[4];
    const float* gn2_w = (const float*)d_in[5];
    const float* gn2_b = (const float*)d_in[6];
    const float* W2    = (const float*)d_in[7];
    const float* b2    = (const float*)d_in[8];
    const float* Wskip = (const float*)d_in[9];
    const float* bskip = (const float*)d_in[10];
    const int* pool_seg = (const int*)d_in[11];
    const int* nbr_idx  = (const int*)d_in[12];
    float* out = (float*)d_out;

    int N = in_sizes[0] / 128;
    int M = in_sizes[12] / 27;

    float *A, *B, *C, *cnt, *part;
    cudaGetSymbolAddress((void**)&A, g_A);
    cudaGetSymbolAddress((void**)&B, g_B);
    cudaGetSymbolAddress((void**)&C, g_C);
    cudaGetSymbolAddress((void**)&cnt, g_cnt);
    cudaGetSymbolAddress((void**)&part, g_part);
    bf16 *hdh, *hdl, *xdh, *xdl, *h2h, *h2l, *W1h, *W1l, *W2h, *W2l, *WSh, *WSl;
    cudaGetSymbolAddress((void**)&hdh, g_hdh);
    cudaGetSymbolAddress((void**)&hdl, g_hdl);
    cudaGetSymbolAddress((void**)&xdh, g_xdh);
    cudaGetSymbolAddress((void**)&xdl, g_xdl);
    cudaGetSymbolAddress((void**)&h2h, g_h2h);
    cudaGetSymbolAddress((void**)&h2l, g_h2l);
    cudaGetSymbolAddress((void**)&W1h, g_W1h);
    cudaGetSymbolAddress((void**)&W1l, g_W1l);
    cudaGetSymbolAddress((void**)&W2h, g_W2h);
    cudaGetSymbolAddress((void**)&W2l, g_W2l);
    cudaGetSymbolAddress((void**)&WSh, g_WSh);
    cudaGetSymbolAddress((void**)&WSl, g_WSl);

    // dynamic smem: conv1 = 2*16K + 80K + 256 ; conv2 = 2*32K + 80K + 256
    const int SM1 = 2 * (64 * 128 * 2) + 2 * (2 * 256 * 80) + 256;
    const int SM2 = 2 * (64 * 256 * 2) + 2 * (2 * 256 * 80) + 256;
    cudaFuncSetAttribute(conv_hmma<128, false>,
                         cudaFuncAttributeMaxDynamicSharedMemorySize, SM1);
    cudaFuncSetAttribute(conv_hmma<256, true>,
                         cudaFuncAttributeMaxDynamicSharedMemorySize, SM2);

    // zero atomic accumulators (graph replays -> re-zero every launch)
    zero_kernel<<<4096, 256>>>(A, (size_t)M * 128);
    zero_kernel<<<4096, 256>>>(B, (size_t)M * 128);
    zero_kernel<<<256, 256>>>(cnt, (size_t)M);

    // weight transpose + bf16 hi/lo split
    prep_w<128><<<1024, 256>>>(W1, W1h, W1l, 27 * 256 * 128);
    prep_w<256><<<2048, 256>>>(W2, W2h, W2l, 27 * 256 * 256);
    prep_w<128><<<128, 256>>>(Wskip, WSh, WSl, 256 * 128);

    // GN1 stats + finalize
    gn_stats<128><<<NB, 256>>>(feats, N, part);
    gn_finalize<128, 4><<<1, 128>>>(part, gn1_w, gn1_b, 1.f / ((float)N * 4.f));

    // GN1 apply + SiLU + segment sums; then means + hi/lo planes
    long dthreads = (long)N * 32;
    downsample_kernel<<<(int)((dthreads + 255) / 256), 256>>>(feats, pool_seg, N);
    long fthreads = (long)M * 32;
    finalize_down<<<(int)((fthreads + 255) / 256), 256>>>(M);

    int nconv = (M + 63) / 64;

    // conv1: h1 = conv(h_d, W1) + b1
    conv_hmma<128, false><<<nconv, 256, SM1>>>(
        hdh, hdl, W1h, W1l, nullptr, nullptr, nullptr, nullptr,
        b1, nullptr, nbr_idx, C, M);

    // GN2 stats + finalize + apply (emits h2 hi/lo planes)
    gn_stats<256><<<NB, 256>>>(C, M, part);
    gn_finalize<256, 8><<<1, 256>>>(part, gn2_w, gn2_b, 1.f / ((float)M * 8.f));
    long athreads = (long)M * 64;
    apply_gn2<<<(int)((athreads + 255) / 256), 256>>>(M);

    // conv2 + fused skip: out = conv(h2, W2) + b2 + x_d @ Wskip + bskip
    conv_hmma<256, true><<<nconv, 256, SM2>>>(
        h2h, h2l, W2h, W2l, xdh, xdl, WSh, WSl,
        b2, bskip, nbr_idx, out, M);
}